// round 2
// baseline (speedup 1.0000x reference)
#include <cuda_runtime.h>
#include <math.h>

// Problem constants (fixed by the reference setup_inputs):
//   B=16, Tq=Tk=1024, H=1024. All GEMM dims are multiples of 128 -> no bounds checks.
#define BATCH 16
#define TSEQ  1024
#define HDIM  1024

// Scratch: q buffer [B*Tq, H] and score buffer [B, Tq, Tk], softmax done in-place on g_s.
__device__ float g_q[BATCH * TSEQ * HDIM];   // 64 MB
__device__ float g_s[BATCH * TSEQ * TSEQ];   // 64 MB

// ---------------------------------------------------------------------------
// SIMT fp32 GEMM: C = A * B(^T) (+ bias), 128x128x16 tiles, 256 threads,
// 8x8 per-thread microtile with split 4+4 column mapping, double-buffered smem.
//   TRANSB = true : B is [N,K] row-major (K contiguous)  -> C = A * B^T
//   TRANSB = false: B is [K,N] row-major (N contiguous)  -> C = A * B
// ---------------------------------------------------------------------------
template <bool TRANSB, bool BIAS>
__global__ __launch_bounds__(256, 2)
void sgemm_kernel(const float* __restrict__ A,
                  const float* __restrict__ Bm,
                  float* __restrict__ C,
                  const float* __restrict__ bias,
                  int M, int N, int K,
                  size_t strideA, size_t strideB, size_t strideC)
{
    __shared__ float As[2][16][128];   // [stage][k][m]
    __shared__ float Bs[2][16][128];   // [stage][k][n]

    const int bx = blockIdx.x;   // N tile
    const int by = blockIdx.y;   // M tile
    const int bz = blockIdx.z;   // batch

    A  += (size_t)bz * strideA;
    Bm += (size_t)bz * strideB;
    C  += (size_t)bz * strideC;

    const int tid = threadIdx.x;
    const int tx  = tid & 15;    // 0..15 -> column group
    const int ty  = tid >> 4;    // 0..15 -> row group

    const float* Aptr = A + (size_t)by * 128 * K;
    const float* Bptr = TRANSB ? (Bm + (size_t)bx * 128 * K)
                               : (Bm + (size_t)bx * 128);

    float acc[8][8];
    #pragma unroll
    for (int i = 0; i < 8; i++)
        #pragma unroll
        for (int j = 0; j < 8; j++)
            acc[i][j] = 0.f;

    float4 pa[2], pb[2];

    auto loadA = [&](int kt) {
        #pragma unroll
        for (int u = 0; u < 2; u++) {
            int i   = tid + u * 256;          // float4 index in 128x16 tile
            int row = i >> 2;
            int c4  = i & 3;
            pa[u] = *(const float4*)(Aptr + (size_t)row * K + kt * 16 + c4 * 4);
        }
    };
    auto loadB = [&](int kt) {
        if (TRANSB) {
            #pragma unroll
            for (int u = 0; u < 2; u++) {
                int i   = tid + u * 256;
                int row = i >> 2;
                int c4  = i & 3;
                pb[u] = *(const float4*)(Bptr + (size_t)row * K + kt * 16 + c4 * 4);
            }
        } else {
            #pragma unroll
            for (int u = 0; u < 2; u++) {
                int i  = tid + u * 256;       // float4 index in 16x128 tile
                int k  = i >> 5;
                int n4 = i & 31;
                pb[u] = *(const float4*)(Bptr + (size_t)(kt * 16 + k) * N + n4 * 4);
            }
        }
    };
    auto storeAB = [&](int st) {
        #pragma unroll
        for (int u = 0; u < 2; u++) {
            int i   = tid + u * 256;
            int row = i >> 2;
            int c4  = i & 3;
            As[st][c4 * 4 + 0][row] = pa[u].x;
            As[st][c4 * 4 + 1][row] = pa[u].y;
            As[st][c4 * 4 + 2][row] = pa[u].z;
            As[st][c4 * 4 + 3][row] = pa[u].w;
        }
        if (TRANSB) {
            #pragma unroll
            for (int u = 0; u < 2; u++) {
                int i   = tid + u * 256;
                int row = i >> 2;
                int c4  = i & 3;
                Bs[st][c4 * 4 + 0][row] = pb[u].x;
                Bs[st][c4 * 4 + 1][row] = pb[u].y;
                Bs[st][c4 * 4 + 2][row] = pb[u].z;
                Bs[st][c4 * 4 + 3][row] = pb[u].w;
            }
        } else {
            #pragma unroll
            for (int u = 0; u < 2; u++) {
                int i  = tid + u * 256;
                int k  = i >> 5;
                int n4 = i & 31;
                *(float4*)&Bs[st][k][n4 * 4] = pb[u];
            }
        }
    };
    auto compute = [&](int st) {
        #pragma unroll
        for (int kk = 0; kk < 16; kk++) {
            float a[8], b[8];
            *(float4*)&a[0] = *(const float4*)&As[st][kk][ty * 8];
            *(float4*)&a[4] = *(const float4*)&As[st][kk][ty * 8 + 4];
            *(float4*)&b[0] = *(const float4*)&Bs[st][kk][tx * 4];
            *(float4*)&b[4] = *(const float4*)&Bs[st][kk][tx * 4 + 64];
            #pragma unroll
            for (int i = 0; i < 8; i++)
                #pragma unroll
                for (int j = 0; j < 8; j++)
                    acc[i][j] += a[i] * b[j];
        }
    };

    const int NT = K / 16;
    loadA(0); loadB(0);
    storeAB(0);
    __syncthreads();

    int st = 0;
    for (int kt = 1; kt < NT; kt++) {
        loadA(kt); loadB(kt);      // gmem prefetch into regs (overlaps compute)
        compute(st);               // consume current stage
        storeAB(st ^ 1);           // fill other stage (no barrier needed before:
                                   //   other stage was consumed 1 iter ago)
        __syncthreads();           // single barrier per iteration
        st ^= 1;
    }
    compute(st);

    // Epilogue: split 4+4 columns (tx*4 and tx*4+64)
    #pragma unroll
    for (int i = 0; i < 8; i++) {
        int row  = by * 128 + ty * 8 + i;
        int col0 = bx * 128 + tx * 4;
        float4 c0 = make_float4(acc[i][0], acc[i][1], acc[i][2], acc[i][3]);
        float4 c1 = make_float4(acc[i][4], acc[i][5], acc[i][6], acc[i][7]);
        if (BIAS) {
            c0.x += bias[col0 + 0];  c0.y += bias[col0 + 1];
            c0.z += bias[col0 + 2];  c0.w += bias[col0 + 3];
            c1.x += bias[col0 + 64]; c1.y += bias[col0 + 65];
            c1.z += bias[col0 + 66]; c1.w += bias[col0 + 67];
        }
        *(float4*)(C + (size_t)row * N + col0)      = c0;
        *(float4*)(C + (size_t)row * N + col0 + 64) = c1;
    }
}

// ---------------------------------------------------------------------------
// Masked softmax over each score row (Tk = 1024), in place.
// One 256-thread block per (b, q) row; 4 elements/thread.
// mask[b][k] != 0  ->  score := -inf (weight := 0)
// ---------------------------------------------------------------------------
__global__ void softmax_mask_kernel(float* __restrict__ S,
                                    const int* __restrict__ mask)
{
    const int row = blockIdx.x;          // b * TSEQ + q
    const int b   = row >> 10;
    float* srow = S + (size_t)row * TSEQ;
    const int* mrow = mask + b * TSEQ;

    const int tid = threadIdx.x;
    __shared__ float red[8];

    float v[4];
    int   m[4];
    float mx = -INFINITY;
    #pragma unroll
    for (int u = 0; u < 4; u++) {
        int k = tid + u * 256;
        m[u] = mrow[k];
        float vv = m[u] ? -INFINITY : srow[k];
        v[u] = vv;
        mx = fmaxf(mx, vv);
    }

    // block max
    #pragma unroll
    for (int o = 16; o; o >>= 1)
        mx = fmaxf(mx, __shfl_xor_sync(0xffffffff, mx, o));
    if ((tid & 31) == 0) red[tid >> 5] = mx;
    __syncthreads();
    float bmax = -INFINITY;
    #pragma unroll
    for (int i = 0; i < 8; i++) bmax = fmaxf(bmax, red[i]);
    __syncthreads();

    // exp and sum
    float s = 0.f;
    #pragma unroll
    for (int u = 0; u < 4; u++) {
        float e = m[u] ? 0.f : __expf(v[u] - bmax);
        v[u] = e;
        s += e;
    }
    #pragma unroll
    for (int o = 16; o; o >>= 1)
        s += __shfl_xor_sync(0xffffffff, s, o);
    if ((tid & 31) == 0) red[tid >> 5] = s;
    __syncthreads();
    float bsum = 0.f;
    #pragma unroll
    for (int i = 0; i < 8; i++) bsum += red[i];

    float rinv = 1.f / bsum;
    #pragma unroll
    for (int u = 0; u < 4; u++)
        srow[tid + u * 256] = v[u] * rinv;
}

// ---------------------------------------------------------------------------
// kernel_launch: 4 graph-capturable launches, no allocs, no syncs.
// Inputs (metadata order): h_t_dec f32[16,1024,1024], x_enc f32[16,1024,1024],
//                          mask int32[16,1024], W f32[1024,1024], b f32[1024]
// Output: context f32[16,1024,1024]
// ---------------------------------------------------------------------------
extern "C" void kernel_launch(void* const* d_in, const int* in_sizes, int n_in,
                              void* d_out, int out_size)
{
    const float* h    = (const float*)d_in[0];
    const float* x    = (const float*)d_in[1];
    const int*   mask = (const int*)  d_in[2];
    const float* W    = (const float*)d_in[3];
    const float* bv   = (const float*)d_in[4];
    float* out = (float*)d_out;

    float *q, *s;
    cudaGetSymbolAddress((void**)&q, g_q);
    cudaGetSymbolAddress((void**)&s, g_s);

    dim3 blk(256);
    const size_t TT = (size_t)TSEQ * TSEQ;       // 1M
    const size_t TH = (size_t)TSEQ * HDIM;       // 1M

    // 1) q = h @ W^T + b    (M = B*Tq = 16384, N = H, K = H)
    sgemm_kernel<true, true><<<dim3(HDIM / 128, (BATCH * TSEQ) / 128, 1), blk>>>(
        h, W, q, bv, BATCH * TSEQ, HDIM, HDIM, 0, 0, 0);

    // 2) S[b] = q[b] @ x[b]^T   (batched NT)
    sgemm_kernel<true, false><<<dim3(TSEQ / 128, TSEQ / 128, BATCH), blk>>>(
        q, x, s, nullptr, TSEQ, TSEQ, HDIM, TH, TH, TT);

    // 3) masked softmax over each score row, in place
    softmax_mask_kernel<<<BATCH * TSEQ, 256>>>(s, mask);

    // 4) out[b] = P[b] @ x[b]   (batched NN)
    sgemm_kernel<false, false><<<dim3(HDIM / 128, TSEQ / 128, BATCH), blk>>>(
        s, x, out, nullptr, TSEQ, HDIM, TSEQ, TT, TH, TH);
}

// round 4
// speedup vs baseline: 1.8933x; 1.8933x over previous
#include <cuda_runtime.h>
#include <cuda_fp16.h>
#include <math.h>
#include <stdint.h>

// Problem constants (fixed): B=16, Tq=Tk=H=1024.
#define BATCH 16
#define TSEQ  1024
#define HDIM  1024
#define NELEM (BATCH * TSEQ * HDIM)   // 16M

// Scratch (device globals; no allocs allowed)
__device__ float  g_s  [NELEM];                         // scores f32
__device__ __half g_hh [NELEM],        g_hl [NELEM];    // h split
__device__ __half g_Wh [HDIM * HDIM],  g_Wl [HDIM * HDIM];
__device__ __half g_qh [NELEM],        g_ql [NELEM];    // q split (GEMM1 epilogue)
__device__ __half g_xh [NELEM],        g_xl [NELEM];    // x split
__device__ __half g_xTh[NELEM],        g_xTl[NELEM];    // x^T split
__device__ __half g_Ph [NELEM],        g_Pl [NELEM];    // softmax weights split

// ---------------------------------------------------------------------------
// helpers
// ---------------------------------------------------------------------------
__device__ __forceinline__ uint32_t smem_u32(const void* p) {
    uint32_t a;
    asm("{ .reg .u64 t; cvta.to.shared.u64 t, %1; cvt.u32.u64 %0, t; }" : "=r"(a) : "l"(p));
    return a;
}
__device__ __forceinline__ void split1(float a, __half& h, __half& l) {
    h = __float2half_rn(a);
    l = __float2half_rn(a - __half2float(h));
}
__device__ __forceinline__ void ldsm4(uint32_t& r0, uint32_t& r1, uint32_t& r2,
                                      uint32_t& r3, uint32_t addr) {
    asm volatile("ldmatrix.sync.aligned.m8n8.x4.shared.b16 {%0,%1,%2,%3}, [%4];"
                 : "=r"(r0), "=r"(r1), "=r"(r2), "=r"(r3) : "r"(addr));
}
__device__ __forceinline__ void mma16816(float* d, const uint32_t* a,
                                         uint32_t b0, uint32_t b1) {
    asm volatile(
        "mma.sync.aligned.m16n8k16.row.col.f32.f16.f16.f32 "
        "{%0,%1,%2,%3}, {%4,%5,%6,%7}, {%8,%9}, {%0,%1,%2,%3};"
        : "+f"(d[0]), "+f"(d[1]), "+f"(d[2]), "+f"(d[3])
        : "r"(a[0]), "r"(a[1]), "r"(a[2]), "r"(a[3]), "r"(b0), "r"(b1));
}
#define CP16(sa, gp) asm volatile("cp.async.cg.shared.global [%0], [%1], 16;" :: "r"(sa), "l"(gp) : "memory")
#define CP_COMMIT()  asm volatile("cp.async.commit_group;" ::: "memory")
#define CP_WAIT(N)   asm volatile("cp.async.wait_group %0;" :: "n"(N) : "memory")

// ---------------------------------------------------------------------------
// Split-fp16 HMMA GEMM:  C[M,1024] = A[M,1024] * B[1024,1024]^T   (NT, K contig)
// Inputs pre-split (hi/lo half arrays). CTA 128x128, K-chunk 32, 8 warps (64x32),
// 2-stage cp.async pipeline. Smem rows padded to 80B (conflict-free ldmatrix).
// MODE 0: C fp32. MODE 1: bias add + write hi/lo half pair (for q).
// ---------------------------------------------------------------------------
#define KCH    32
#define NCHUNK (HDIM / KCH)    // 32
#define TILEB  10240           // 128 rows * 80 B
#define STAGEB (4 * TILEB)     // Ah, Al, Bh, Bl
#define SMEMB  (2 * STAGEB)    // 81920

template <int MODE>
__global__ __launch_bounds__(256)
void hgemm(const __half* __restrict__ Agh, const __half* __restrict__ Agl,
           const __half* __restrict__ Bgh, const __half* __restrict__ Bgl,
           float* __restrict__ C, const float* __restrict__ bias,
           __half* __restrict__ Coh, __half* __restrict__ Col,
           size_t sA, size_t sB, size_t sC)
{
    extern __shared__ char sm[];
    const uint32_t sbase = smem_u32(sm);
    const int tid  = threadIdx.x;
    const int lane = tid & 31, wid = tid >> 5;
    const int bx = blockIdx.x, by = blockIdx.y, bz = blockIdx.z;
    const int wm = wid & 1, wn = wid >> 1;     // warp grid 2(M) x 4(N)

    // ---- global->smem load mapping: 512 x 16B units per tile, 2 per thread
    const int row0 = tid >> 2;       // 0..63 (unit u=1 adds 64)
    const int seg  = tid & 3;        // 16B segment within 64B row
    const size_t gstep = (size_t)row0 * 1024 + seg * 8;   // halves
    const __half* pAh = Agh + bz * sA + (size_t)(by * 128) * 1024 + gstep;
    const __half* pAl = Agl + bz * sA + (size_t)(by * 128) * 1024 + gstep;
    const __half* pBh = Bgh + bz * sB + (size_t)(bx * 128) * 1024 + gstep;
    const __half* pBl = Bgl + bz * sB + (size_t)(bx * 128) * 1024 + gstep;
    const uint32_t soff = row0 * 80 + seg * 16;

    auto issue_loads = [&](int kt, int s) {
        const uint32_t sb = sbase + s * STAGEB + soff;
        const size_t ko = (size_t)kt * KCH;
        CP16(sb,                     pAh + ko);
        CP16(sb + 5120,              pAh + ko + 65536);   // +64 rows
        CP16(sb + TILEB,             pAl + ko);
        CP16(sb + TILEB + 5120,      pAl + ko + 65536);
        CP16(sb + 2 * TILEB,         pBh + ko);
        CP16(sb + 2 * TILEB + 5120,  pBh + ko + 65536);
        CP16(sb + 3 * TILEB,         pBl + ko);
        CP16(sb + 3 * TILEB + 5120,  pBl + ko + 65536);
    };

    float acc[4][4][4];
    #pragma unroll
    for (int i = 0; i < 4; i++)
        #pragma unroll
        for (int j = 0; j < 4; j++)
            #pragma unroll
            for (int k = 0; k < 4; k++) acc[i][j][k] = 0.f;

    // ldmatrix per-lane address pieces
    const int lr = lane & 15;                 // row within 16-row block
    const int lc = ((lane >> 4) & 1) * 16;    // 8-col (16B) segment

    issue_loads(0, 0);
    CP_COMMIT();

    for (int kt = 0; kt < NCHUNK; kt++) {
        if (kt + 1 < NCHUNK) {
            issue_loads(kt + 1, (kt + 1) & 1);
            CP_COMMIT();
            CP_WAIT(1);
        } else {
            CP_WAIT(0);
        }
        __syncthreads();

        // ---- compute on stage kt&1
        const uint32_t stb = sbase + (kt & 1) * STAGEB;
        const uint32_t aAh = stb + (wm * 64 + lr) * 80 + lc;
        const uint32_t aAl = aAh + TILEB;
        const uint32_t aBh = stb + 2 * TILEB + (wn * 32 + lr) * 80 + lc;
        const uint32_t aBl = aBh + TILEB;

        #pragma unroll
        for (int k0 = 0; k0 < 2; k0++) {
            const int ko = k0 * 32;   // 16 halves = 32 bytes
            uint32_t ah[4][4], al[4][4];
            #pragma unroll
            for (int mf = 0; mf < 4; mf++) {
                ldsm4(ah[mf][0], ah[mf][1], ah[mf][2], ah[mf][3], aAh + mf * 1280 + ko);
                ldsm4(al[mf][0], al[mf][1], al[mf][2], al[mf][3], aAl + mf * 1280 + ko);
            }
            #pragma unroll
            for (int nb = 0; nb < 2; nb++) {
                uint32_t bh0, bh1, bh2, bh3, bl0, bl1, bl2, bl3;
                ldsm4(bh0, bh1, bh2, bh3, aBh + nb * 1280 + ko);
                ldsm4(bl0, bl1, bl2, bl3, aBl + nb * 1280 + ko);
                // term hh
                #pragma unroll
                for (int mf = 0; mf < 4; mf++) {
                    mma16816(acc[mf][2 * nb],     ah[mf], bh0, bh2);
                    mma16816(acc[mf][2 * nb + 1], ah[mf], bh1, bh3);
                }
                // term hl
                #pragma unroll
                for (int mf = 0; mf < 4; mf++) {
                    mma16816(acc[mf][2 * nb],     ah[mf], bl0, bl2);
                    mma16816(acc[mf][2 * nb + 1], ah[mf], bl1, bl3);
                }
                // term lh
                #pragma unroll
                for (int mf = 0; mf < 4; mf++) {
                    mma16816(acc[mf][2 * nb],     al[mf], bh0, bh2);
                    mma16816(acc[mf][2 * nb + 1], al[mf], bh1, bh3);
                }
            }
        }
        __syncthreads();
    }

    // ---- epilogue
    const int quad = lane >> 2, tq = lane & 3;
    const int m0 = by * 128 + wm * 64;
    const int n0 = bx * 128 + wn * 32;
    #pragma unroll
    for (int mf = 0; mf < 4; mf++) {
        #pragma unroll
        for (int nf = 0; nf < 4; nf++) {
            const int r   = m0 + mf * 16 + quad;
            const int col = n0 + nf * 8 + tq * 2;
            float* a4 = acc[mf][nf];
            if (MODE == 0) {
                const size_t o = bz * sC + (size_t)r * 1024 + col;
                *(float2*)(C + o)            = make_float2(a4[0], a4[1]);
                *(float2*)(C + o + 8 * 1024) = make_float2(a4[2], a4[3]);
            } else {
                const float b0 = bias[col], b1 = bias[col + 1];
                __half h0, l0, h1, l1;
                const size_t o = bz * sC + (size_t)r * 1024 + col;
                split1(a4[0] + b0, h0, l0); split1(a4[1] + b1, h1, l1);
                *(__half2*)(Coh + o) = __halves2half2(h0, h1);
                *(__half2*)(Col + o) = __halves2half2(l0, l1);
                split1(a4[2] + b0, h0, l0); split1(a4[3] + b1, h1, l1);
                *(__half2*)(Coh + o + 8 * 1024) = __halves2half2(h0, h1);
                *(__half2*)(Col + o + 8 * 1024) = __halves2half2(l0, l1);
            }
        }
    }
}

// ---------------------------------------------------------------------------
// fp32 -> (hi, lo) fp16 split, vectorized
// ---------------------------------------------------------------------------
__global__ void split_kernel(const float* __restrict__ in, __half* __restrict__ hi,
                             __half* __restrict__ lo, int n4)
{
    int i = blockIdx.x * 256 + threadIdx.x;
    if (i >= n4) return;
    float4 v = ((const float4*)in)[i];
    __half hx, lx, hy, ly, hz, lz, hw, lw;
    split1(v.x, hx, lx); split1(v.y, hy, ly);
    split1(v.z, hz, lz); split1(v.w, hw, lw);
    __half2* H = (__half2*)hi; __half2* L = (__half2*)lo;
    H[2 * i] = __halves2half2(hx, hy); H[2 * i + 1] = __halves2half2(hz, hw);
    L[2 * i] = __halves2half2(lx, ly); L[2 * i + 1] = __halves2half2(lz, lw);
}

// ---------------------------------------------------------------------------
// x [B,Tk,H] -> xT hi/lo [B,H,Tk]
// ---------------------------------------------------------------------------
__global__ void transpose_split_kernel(const float* __restrict__ x,
                                       __half* __restrict__ xTh, __half* __restrict__ xTl)
{
    __shared__ float t[32][33];
    const int b = blockIdx.z;
    const int k0 = blockIdx.y * 32, h0 = blockIdx.x * 32;
    const float* xp = x + (size_t)b * TSEQ * HDIM;
    __half* oh = xTh + (size_t)b * HDIM * TSEQ;
    __half* ol = xTl + (size_t)b * HDIM * TSEQ;
    const int lx = threadIdx.x, ly = threadIdx.y;
    #pragma unroll
    for (int i = 0; i < 32; i += 8)
        t[ly + i][lx] = xp[(size_t)(k0 + ly + i) * HDIM + h0 + lx];
    __syncthreads();
    #pragma unroll
    for (int i = 0; i < 32; i += 8) {
        float v = t[lx][ly + i];
        __half h, l; split1(v, h, l);
        oh[(size_t)(h0 + ly + i) * TSEQ + k0 + lx] = h;
        ol[(size_t)(h0 + ly + i) * TSEQ + k0 + lx] = l;
    }
}

// ---------------------------------------------------------------------------
// Masked softmax over each score row (Tk=1024); writes hi/lo half weights.
// ---------------------------------------------------------------------------
__global__ void softmax_mask_kernel(const float* __restrict__ S, const int* __restrict__ mask,
                                    __half* __restrict__ Ph, __half* __restrict__ Pl)
{
    const int row = blockIdx.x;
    const int b = row >> 10;
    const float* srow = S + (size_t)row * TSEQ;
    __half* ph = Ph + (size_t)row * TSEQ;
    __half* pl = Pl + (size_t)row * TSEQ;
    const int* mrow = mask + b * TSEQ;
    const int tid = threadIdx.x;
    __shared__ float red[8];

    float v[4]; int m[4];
    float mx = -INFINITY;
    #pragma unroll
    for (int u = 0; u < 4; u++) {
        int k = tid + u * 256;
        m[u] = mrow[k];
        float vv = m[u] ? -INFINITY : srow[k];
        v[u] = vv;
        mx = fmaxf(mx, vv);
    }
    #pragma unroll
    for (int o = 16; o; o >>= 1) mx = fmaxf(mx, __shfl_xor_sync(0xffffffff, mx, o));
    if ((tid & 31) == 0) red[tid >> 5] = mx;
    __syncthreads();
    float bmax = -INFINITY;
    #pragma unroll
    for (int i = 0; i < 8; i++) bmax = fmaxf(bmax, red[i]);
    __syncthreads();

    float s = 0.f;
    #pragma unroll
    for (int u = 0; u < 4; u++) {
        float e = m[u] ? 0.f : __expf(v[u] - bmax);
        v[u] = e; s += e;
    }
    #pragma unroll
    for (int o = 16; o; o >>= 1) s += __shfl_xor_sync(0xffffffff, s, o);
    if ((tid & 31) == 0) red[tid >> 5] = s;
    __syncthreads();
    float bsum = 0.f;
    #pragma unroll
    for (int i = 0; i < 8; i++) bsum += red[i];

    const float rinv = 1.f / bsum;
    #pragma unroll
    for (int u = 0; u < 4; u++) {
        float w = v[u] * rinv;
        __half h, l; split1(w, h, l);
        ph[tid + u * 256] = h;
        pl[tid + u * 256] = l;
    }
}

// ---------------------------------------------------------------------------
// kernel_launch
// ---------------------------------------------------------------------------
extern "C" void kernel_launch(void* const* d_in, const int* in_sizes, int n_in,
                              void* d_out, int out_size)
{
    const float* h    = (const float*)d_in[0];
    const float* x    = (const float*)d_in[1];
    const int*   mask = (const int*)  d_in[2];
    const float* W    = (const float*)d_in[3];
    const float* bv   = (const float*)d_in[4];
    float* out = (float*)d_out;

    float *s;
    __half *hh, *hl, *Wh, *Wl, *qh, *ql, *xh, *xl, *xTh, *xTl, *Ph, *Pl;
    cudaGetSymbolAddress((void**)&s,   g_s);
    cudaGetSymbolAddress((void**)&hh,  g_hh);  cudaGetSymbolAddress((void**)&hl,  g_hl);
    cudaGetSymbolAddress((void**)&Wh,  g_Wh);  cudaGetSymbolAddress((void**)&Wl,  g_Wl);
    cudaGetSymbolAddress((void**)&qh,  g_qh);  cudaGetSymbolAddress((void**)&ql,  g_ql);
    cudaGetSymbolAddress((void**)&xh,  g_xh);  cudaGetSymbolAddress((void**)&xl,  g_xl);
    cudaGetSymbolAddress((void**)&xTh, g_xTh); cudaGetSymbolAddress((void**)&xTl, g_xTl);
    cudaGetSymbolAddress((void**)&Ph,  g_Ph);  cudaGetSymbolAddress((void**)&Pl,  g_Pl);

    cudaFuncSetAttribute(hgemm<0>, cudaFuncAttributeMaxDynamicSharedMemorySize, SMEMB);
    cudaFuncSetAttribute(hgemm<1>, cudaFuncAttributeMaxDynamicSharedMemorySize, SMEMB);

    const size_t TH = (size_t)TSEQ * HDIM;   // 1M

    // 0) input splits
    split_kernel<<<NELEM / 4 / 256, 256>>>(h, hh, hl, NELEM / 4);
    split_kernel<<<HDIM * HDIM / 4 / 256, 256>>>(W, Wh, Wl, HDIM * HDIM / 4);
    split_kernel<<<NELEM / 4 / 256, 256>>>(x, xh, xl, NELEM / 4);
    transpose_split_kernel<<<dim3(HDIM / 32, TSEQ / 32, BATCH), dim3(32, 8)>>>(x, xTh, xTl);

    // 1) q = h @ W^T + b  -> qh/ql   (M = 16384)
    hgemm<1><<<dim3(8, 128, 1), 256, SMEMB>>>(hh, hl, Wh, Wl,
                                              nullptr, bv, qh, ql, 0, 0, 0);

    // 2) S[b] = q[b] @ x[b]^T  (f32 scores)
    hgemm<0><<<dim3(8, 8, BATCH), 256, SMEMB>>>(qh, ql, xh, xl,
                                                s, nullptr, nullptr, nullptr, TH, TH, TH);

    // 3) masked softmax -> Ph/Pl
    softmax_mask_kernel<<<BATCH * TSEQ, 256>>>(s, mask, Ph, Pl);

    // 4) out[b] = P[b] @ xT[b]^T = P[b] @ x[b]
    hgemm<0><<<dim3(8, 8, BATCH), 256, SMEMB>>>(Ph, Pl, xTh, xTl,
                                                out, nullptr, nullptr, nullptr, TH, TH, TH);
}